// round 3
// baseline (speedup 1.0000x reference)
#include <cuda_runtime.h>

// NSSTDecomposition: 3 grouped conv banks + lowpass channel.
// Input : rgb_image (4,3,512,512) f32, f0 (12,1,11,11), f1 (24,1,15,15), f2 (48,1,19,19)
// Output: (4,87,512,512) f32, channel layout per color c: [4 dirs s0][8 dirs s1][16 dirs s2][low]

#define TILE   32
#define HALO   9                 // max radius (19x19 -> 9)
#define IN_DIM (TILE + 2*HALO)   // 50
#define IMG_W  512
#define IMG_HW (512*512)

// Lowpass scratch: (4,3,128,128) f32  (static device array: allocation-free)
__device__ float g_low[4*3*128*128];

// ---------------------------------------------------------------------------
// Per-scale direct conv over a 32x32 tile resident in smem.
// Thread layout: tx = tid&31 (x), ty = tid>>5 (0..7), each thread does 4 rows
// (y = ty + j*8). DC direction accumulators per thread.
// ---------------------------------------------------------------------------
template<int K, int D, int DC>
__device__ __forceinline__ void conv_scale(
    const float* __restrict__ s_in,
    const float* __restrict__ s_w,
    float* __restrict__ out, int out_base,
    int tx, int ty, int x0, int y0)
{
    const int R   = K / 2;
    const int off = HALO - R;

    #pragma unroll
    for (int d0 = 0; d0 < D; d0 += DC) {
        float acc[DC][4];
        #pragma unroll
        for (int dd = 0; dd < DC; dd++)
            #pragma unroll
            for (int j = 0; j < 4; j++) acc[dd][j] = 0.0f;

        const float* wbase = s_w + d0 * K * K;

        for (int ky = 0; ky < K; ky++) {
            const float* inrow = s_in + (ty + off + ky) * IN_DIM + (tx + off);
            const float* wrow  = wbase + ky * K;
            for (int kx = 0; kx < K; kx++) {
                float w[DC];
                #pragma unroll
                for (int dd = 0; dd < DC; dd++)
                    w[dd] = wrow[dd * K * K + kx];
                #pragma unroll
                for (int j = 0; j < 4; j++) {
                    float v = inrow[j * 8 * IN_DIM + kx];
                    #pragma unroll
                    for (int dd = 0; dd < DC; dd++)
                        acc[dd][j] = fmaf(v, w[dd], acc[dd][j]);
                }
            }
        }

        // Coalesced writes: consecutive tx -> consecutive x.
        #pragma unroll
        for (int dd = 0; dd < DC; dd++) {
            #pragma unroll
            for (int j = 0; j < 4; j++) {
                int y = y0 + ty + j * 8;
                int x = x0 + tx;
                out[out_base + (d0 + dd) * IMG_HW + y * IMG_W + x] = acc[dd][j];
            }
        }
    }
}

__global__ void __launch_bounds__(256)
nsst_conv_kernel(const float* __restrict__ img,
                 const float* __restrict__ f0,
                 const float* __restrict__ f1,
                 const float* __restrict__ f2,
                 float* __restrict__ out)
{
    __shared__ float s_in[IN_DIM * IN_DIM];     // 2500 f = 10 KB
    __shared__ float s_w[16 * 19 * 19];         // 5776 f = 23.1 KB (max scale)

    const int tid = threadIdx.x;
    const int bz  = blockIdx.z;
    const int b   = bz / 3;
    const int c   = bz % 3;
    const int x0  = blockIdx.x * TILE;
    const int y0  = blockIdx.y * TILE;

    // Load 50x50 input tile with zero padding ("same" conv).
    const float* src = img + (b * 3 + c) * IMG_HW;
    for (int idx = tid; idx < IN_DIM * IN_DIM; idx += 256) {
        int iy = idx / IN_DIM;
        int ix = idx - iy * IN_DIM;
        int gy = y0 + iy - HALO;
        int gx = x0 + ix - HALO;
        float v = 0.0f;
        if ((unsigned)gy < (unsigned)IMG_W && (unsigned)gx < (unsigned)IMG_W)
            v = src[gy * IMG_W + gx];
        s_in[idx] = v;
    }

    const int tx = tid & 31;
    const int ty = tid >> 5;
    const int ch_base = b * 87 + c * 29;

    // ---- scale 0: 4 dirs, 11x11 ----
    {
        const float* f = f0 + c * 4 * 11 * 11;   // group slice for this color
        for (int i = tid; i < 4 * 121; i += 256) s_w[i] = f[i];
        __syncthreads();   // covers s_in too
        conv_scale<11, 4, 4>(s_in, s_w, out, (ch_base + 0) * IMG_HW, tx, ty, x0, y0);
        __syncthreads();
    }
    // ---- scale 1: 8 dirs, 15x15 ----
    {
        const float* f = f1 + c * 8 * 15 * 15;
        for (int i = tid; i < 8 * 225; i += 256) s_w[i] = f[i];
        __syncthreads();
        conv_scale<15, 8, 8>(s_in, s_w, out, (ch_base + 4) * IMG_HW, tx, ty, x0, y0);
        __syncthreads();
    }
    // ---- scale 2: 16 dirs, 19x19 ----
    {
        const float* f = f2 + c * 16 * 19 * 19;
        for (int i = tid; i < 16 * 361; i += 256) s_w[i] = f[i];
        __syncthreads();
        conv_scale<19, 16, 8>(s_in, s_w, out, (ch_base + 12) * IMG_HW, tx, ty, x0, y0);
    }
}

// ---------------------------------------------------------------------------
// Lowpass: 4x4 box mean -> (bc,128,128)
// ---------------------------------------------------------------------------
__global__ void __launch_bounds__(256)
nsst_downsample_kernel(const float* __restrict__ img)
{
    int idx = blockIdx.x * 256 + threadIdx.x;   // 12*128*128 = 196608
    if (idx >= 4 * 3 * 128 * 128) return;
    int X  = idx & 127;
    int Y  = (idx >> 7) & 127;
    int bc = idx >> 14;
    const float* src = img + bc * IMG_HW + (Y * 4) * IMG_W + X * 4;
    float s = 0.0f;
    #pragma unroll
    for (int i = 0; i < 4; i++)
        #pragma unroll
        for (int j = 0; j < 4; j++)
            s += src[i * IMG_W + j];
    g_low[idx] = s * (1.0f / 16.0f);
}

// ---------------------------------------------------------------------------
// Bilinear upsample 128->512, half-pixel centers, clamp-to-edge
// (== jax.image.resize 'linear' with its valid-weight renormalization).
// Writes channel c*29 + 28 for each color.
// ---------------------------------------------------------------------------
__global__ void __launch_bounds__(256)
nsst_upsample_kernel(float* __restrict__ out)
{
    int idx = blockIdx.x * 256 + threadIdx.x;   // 12*512*512 = 3145728
    if (idx >= 4 * 3 * IMG_HW) return;
    int x  = idx & 511;
    int y  = (idx >> 9) & 511;
    int bc = idx >> 18;
    int b  = bc / 3;
    int c  = bc % 3;

    float sy = y * 0.25f - 0.375f;   // (y+0.5)/4 - 0.5
    float sx = x * 0.25f - 0.375f;
    int iy0 = (int)floorf(sy);
    int ix0 = (int)floorf(sx);
    float fy = sy - (float)iy0;
    float fx = sx - (float)ix0;
    int y0c = max(0, min(127, iy0));
    int y1c = max(0, min(127, iy0 + 1));
    int x0c = max(0, min(127, ix0));
    int x1c = max(0, min(127, ix0 + 1));

    const float* L = g_low + bc * 128 * 128;
    float v00 = L[y0c * 128 + x0c];
    float v01 = L[y0c * 128 + x1c];
    float v10 = L[y1c * 128 + x0c];
    float v11 = L[y1c * 128 + x1c];
    float top = v00 + fx * (v01 - v00);
    float bot = v10 + fx * (v11 - v10);
    float val = top + fy * (bot - top);

    out[((b * 87 + c * 29 + 28) * IMG_W + y) * IMG_W + x] = val;
}

// ---------------------------------------------------------------------------
extern "C" void kernel_launch(void* const* d_in, const int* in_sizes, int n_in,
                              void* d_out, int out_size)
{
    const float* img = (const float*)d_in[0];
    const float* f0  = (const float*)d_in[1];
    const float* f1  = (const float*)d_in[2];
    const float* f2  = (const float*)d_in[3];
    float* out = (float*)d_out;

    dim3 grid(IMG_W / TILE, IMG_W / TILE, 4 * 3);   // (16,16,12)
    nsst_conv_kernel<<<grid, 256>>>(img, f0, f1, f2, out);

    nsst_downsample_kernel<<<(4 * 3 * 128 * 128 + 255) / 256, 256>>>(img);
    nsst_upsample_kernel<<<(4 * 3 * IMG_HW + 255) / 256, 256>>>(out);
}